// round 8
// baseline (speedup 1.0000x reference)
#include <cuda_runtime.h>
#include <cuda_bf16.h>
#include <mma.h>
#include <cstdint>

using namespace nvcuda;
using bf16 = __nv_bfloat16;

// ---------------- problem dims --------------------------------------------------
constexpr int B_  = 2;
constexpr int N_  = 2048;
constexpr int D_  = 1024;
constexpr int H_  = 8;
constexpr int DK_ = 128;
constexpr int DV_ = 1024;
constexpr int HDK = H_ * DK_;    // 1024
constexpr int HDV = H_ * DV_;    // 8192
constexpr int HN  = H_ * N_;     // 16384

// ---------------- tiling / smem config -------------------------------------------
constexpr int AST = 72;                   // K-major stage row stride (elems), BK=64
constexpr int BRST = 136;                 // row-major B stage row stride (elems)
constexpr int EP_STRIDE = 136;            // fp32 epilogue stage stride

// proj (128x128, BK=64): A 128x72 + B 128x72 per stage
constexpr int PJ_AB = 128 * AST * 2;               // 18432
constexpr int PJ_STAGE = 2 * PJ_AB;                // 36864
constexpr int PJ_DSMEM = 3 * PJ_STAGE;             // 110592 (2 CTAs/SM: 221KB <= 228KB)

// scores (128x128, BK=64, nk=2): two stages, loaded once
constexpr int SC_DSMEM = 2 * PJ_STAGE;             // 73728 (>= 69632 ep stage)

// AV (64x128, BK=64): A 64x72 (9216B) + B 64x136 (17408B)
constexpr int AV_A_BYTES = 64 * AST * 2;                      // 9216
constexpr int AV_STAGE   = AV_A_BYTES + 64 * BRST * 2;        // 26624
constexpr int AV_DSMEM   = 3 * AV_STAGE;                      // 79872 (>= 34816 ep)

// ---------------- scratch (__device__ globals) ----------------------------------
__device__ bf16 g_xb [(size_t)B_ * N_ * D_];
__device__ bf16 g_wqb[(size_t)H_ * DK_ * D_];
__device__ bf16 g_wkb[(size_t)H_ * DK_ * D_];
__device__ bf16 g_wvb[(size_t)H_ * DV_ * D_];
__device__ bf16 g_Q  [(size_t)B_ * N_ * HDK];
__device__ bf16 g_K  [(size_t)B_ * N_ * HDK];
__device__ bf16 g_V  [(size_t)B_ * N_ * HDV];
__device__ bf16 g_sim[(size_t)B_ * N_ * HN];   // lower-triangle tiles only

// ---------------- fragment types -------------------------------------------------
using FragA  = wmma::fragment<wmma::matrix_a, 16, 16, 16, bf16, wmma::row_major>;
using FragBc = wmma::fragment<wmma::matrix_b, 16, 16, 16, bf16, wmma::col_major>;
using FragBr = wmma::fragment<wmma::matrix_b, 16, 16, 16, bf16, wmma::row_major>;
using FragC  = wmma::fragment<wmma::accumulator, 16, 16, 16, float>;

// ---------------- cp.async helpers -----------------------------------------------
__device__ __forceinline__ uint32_t smem_u32(const void* p) {
    uint32_t a;
    asm("{ .reg .u64 t; cvta.to.shared.u64 t, %1; cvt.u32.u64 %0, t; }"
        : "=r"(a) : "l"(p));
    return a;
}
__device__ __forceinline__ void cp16(uint32_t dst, const void* src) {
    asm volatile("cp.async.cg.shared.global [%0], [%1], 16;"
                 :: "r"(dst), "l"(__cvta_generic_to_global(src)));
}
__device__ __forceinline__ void cp_commit() {
    asm volatile("cp.async.commit_group;" ::: "memory");
}
__device__ __forceinline__ void cp_wait1() {
    asm volatile("cp.async.wait_group 1;" ::: "memory");
}
__device__ __forceinline__ void cp_wait0() {
    asm volatile("cp.async.wait_group 0;" ::: "memory");
}

// 128 rows x 64 cols K-major (row stride 72 elems), 128 threads, 8 cp16 each
__device__ __forceinline__ void ld_A128(uint32_t sdst, const bf16* g, int ld, int tid) {
#pragma unroll
    for (int i = 0; i < 8; ++i) {
        int u = tid + i * 128;
        int r = u >> 3, c8 = u & 7;
        cp16(sdst + (uint32_t)(r * (AST * 2) + c8 * 16), g + (size_t)r * ld + c8 * 8);
    }
}
// 64 rows x 64 cols K-major, 128 threads, 4 cp16 each
__device__ __forceinline__ void ld_A64(uint32_t sdst, const bf16* g, int ld, int tid) {
#pragma unroll
    for (int i = 0; i < 4; ++i) {
        int u = tid + i * 128;
        int r = u >> 3, c8 = u & 7;
        cp16(sdst + (uint32_t)(r * (AST * 2) + c8 * 16), g + (size_t)r * ld + c8 * 8);
    }
}
// 64 rows(k) x 128 cols(n) row-major (row stride 136 elems), 128 threads, 8 cp16 each
__device__ __forceinline__ void ld_Brow(uint32_t sdst, const bf16* g, int ld, int tid) {
#pragma unroll
    for (int i = 0; i < 8; ++i) {
        int u = tid + i * 128;
        int r = u >> 4, c16 = u & 15;
        cp16(sdst + (uint32_t)(r * (BRST * 2) + c16 * 16), g + (size_t)r * ld + c16 * 8);
    }
}

// ---------------- MMA micro-steps (BK = 64) ----------------------------------------
// warp tile 64x64, NT (B col-major view, stride 72)
__device__ __forceinline__ void mma_w64(FragC acc[4][4], const bf16* As, const bf16* Bs,
                                        int wm, int wn) {
#pragma unroll
    for (int ks = 0; ks < 64; ks += 16) {
        FragA a[4];
#pragma unroll
        for (int i = 0; i < 4; ++i)
            wmma::load_matrix_sync(a[i], As + (wm * 64 + i * 16) * AST + ks, AST);
#pragma unroll
        for (int j = 0; j < 4; ++j) {
            FragBc b;
            wmma::load_matrix_sync(b, Bs + (wn * 64 + j * 16) * AST + ks, AST);
#pragma unroll
            for (int i = 0; i < 4; ++i)
                wmma::mma_sync(acc[i][j], a[i], b, acc[i][j]);
        }
    }
}
// warp tile 32x64, B row-major (stride 136) — AV
__device__ __forceinline__ void mma_av(FragC acc[2][4], const bf16* As, const bf16* Bs,
                                       int wm, int wn) {
#pragma unroll
    for (int ks = 0; ks < 64; ks += 16) {
        FragA a[2];
        wmma::load_matrix_sync(a[0], As + (wm * 32) * AST + ks,      AST);
        wmma::load_matrix_sync(a[1], As + (wm * 32 + 16) * AST + ks, AST);
#pragma unroll
        for (int j = 0; j < 4; ++j) {
            FragBr b;
            wmma::load_matrix_sync(b, Bs + ks * BRST + wn * 64 + j * 16, BRST);
            wmma::mma_sync(acc[0][j], a[0], b, acc[0][j]);
            wmma::mma_sync(acc[1][j], a[1], b, acc[1][j]);
        }
    }
}

// ---------------- epilogues (128 threads) ------------------------------------------
__device__ __forceinline__ void stage_acc16(FragC acc[4][4], float* stg, int wm, int wn) {
#pragma unroll
    for (int i = 0; i < 4; ++i)
#pragma unroll
        for (int j = 0; j < 4; ++j)
            wmma::store_matrix_sync(stg + (wm * 64 + i * 16) * EP_STRIDE + wn * 64 + j * 16,
                                    acc[i][j], EP_STRIDE, wmma::mem_row_major);
}

// MODE 0: plain bf16. MODE 1: causal relu/N bf16.
template <int MODE>
__device__ __forceinline__ void ep_bf16(FragC acc[4][4], char* dsm, bf16* C, int ldc,
                                        int q0, int m0, int tid, int wm, int wn) {
    float* stg = reinterpret_cast<float*>(dsm);
    stage_acc16(acc, stg, wm, wn);
    __syncthreads();
    const float inv_n = 1.0f / (float)N_;
#pragma unroll
    for (int it = 0; it < 16; ++it) {
        int idx = it * 128 + tid;
        int r = idx >> 4, cv = idx & 15;
        const float* p = stg + r * EP_STRIDE + cv * 8;
        union { bf16 v[8]; uint4 u4; } pk;
#pragma unroll
        for (int e = 0; e < 8; ++e) {
            float v = p[e];
            if (MODE == 1) {
                int gm = m0 + cv * 8 + e;
                v = (gm <= q0 + r) ? fmaxf(v, 0.0f) * inv_n : 0.0f;
            }
            pk.v[e] = __float2bfloat16(v);
        }
        *reinterpret_cast<uint4*>(C + (size_t)r * ldc + cv * 8) = pk.u4;
    }
    __syncthreads();
}

// ---------------- kernels ---------------------------------------------------------
__global__ void f2bf_kernel(const float4* __restrict__ in,
                            __nv_bfloat162* __restrict__ out, int n4) {
    int i0 = (blockIdx.x * blockDim.x + threadIdx.x) * 2;
#pragma unroll
    for (int k = 0; k < 2; ++k) {
        int i = i0 + k;
        if (i < n4) {
            float4 v = in[i];
            out[2 * i]     = __floats2bfloat162_rn(v.x, v.y);
            out[2 * i + 1] = __floats2bfloat162_rn(v.z, v.w);
        }
    }
}

// projection: C[128x128] = A rows * W rows^T, BK=64, 3-stage ring (prologue 2, wait 1)
__global__ __launch_bounds__(128) void k_proj(const bf16* __restrict__ A0,
                                              const bf16* __restrict__ W,
                                              bf16* __restrict__ C0, int ldc) {
    extern __shared__ char dsm[];
    uint32_t sb = smem_u32(dsm);
    int tid = threadIdx.x, wid = tid >> 5;
    int wm = wid & 1, wn = wid >> 1;
    const bf16* A  = A0 + (size_t)blockIdx.y * 128 * D_;
    const bf16* Bp = W  + (size_t)blockIdx.x * 128 * D_;
    bf16* C = C0 + (size_t)(blockIdx.y * 128) * ldc + blockIdx.x * 128;

    FragC acc[4][4];
#pragma unroll
    for (int i = 0; i < 4; ++i)
#pragma unroll
        for (int j = 0; j < 4; ++j) wmma::fill_fragment(acc[i][j], 0.0f);

    const int nk = D_ / 64;  // 8
#pragma unroll
    for (int s = 0; s < 2; ++s) {
        ld_A128(sb + s * PJ_STAGE,         A  + s * 64, D_, tid);
        ld_A128(sb + s * PJ_STAGE + PJ_AB, Bp + s * 64, D_, tid);
        cp_commit();
    }
    for (int i = 0; i < nk; ++i) {
        cp_wait1();
        __syncthreads();
        int ci = i + 2;
        if (ci < nk) {
            uint32_t st = sb + (uint32_t)(ci % 3) * PJ_STAGE;
            ld_A128(st,         A  + ci * 64, D_, tid);
            ld_A128(st + PJ_AB, Bp + ci * 64, D_, tid);
        }
        cp_commit();
        const bf16* As = reinterpret_cast<const bf16*>(dsm + (i % 3) * PJ_STAGE);
        mma_w64(acc, As, As + PJ_AB / 2, wm, wn);
    }
    cp_wait0();
    __syncthreads();
    ep_bf16<0>(acc, dsm, C, ldc, 0, 0, tid, wm, wn);
}

// causal relu(QK^T)/N -> sim (lower-triangle tiles only), BK=64, nk=2 single-shot
__global__ __launch_bounds__(128) void k_scores(const bf16* __restrict__ Q,
                                                const bf16* __restrict__ Kx,
                                                bf16* __restrict__ sim) {
    int mt = blockIdx.x, nt = blockIdx.y;
    if (mt > nt) return;                       // upper tiles never read by AV
    int b = blockIdx.z >> 3, h = blockIdx.z & 7;
    extern __shared__ char dsm[];
    uint32_t sb = smem_u32(dsm);
    int tid = threadIdx.x, wid = tid >> 5;
    int wm = wid & 1, wn = wid >> 1;

    const bf16* A  = Q  + ((size_t)(b * N_ + nt * 128)) * HDK + h * DK_;
    const bf16* Bp = Kx + ((size_t)(b * N_ + mt * 128)) * HDK + h * DK_;
    bf16* C = sim + ((size_t)(b * N_ + nt * 128)) * HN + (size_t)h * N_ + mt * 128;

    FragC acc[4][4];
#pragma unroll
    for (int i = 0; i < 4; ++i)
#pragma unroll
        for (int j = 0; j < 4; ++j) wmma::fill_fragment(acc[i][j], 0.0f);

#pragma unroll
    for (int s = 0; s < 2; ++s) {
        ld_A128(sb + s * PJ_STAGE,         A  + s * 64, HDK, tid);
        ld_A128(sb + s * PJ_STAGE + PJ_AB, Bp + s * 64, HDK, tid);
        cp_commit();
    }
    cp_wait0();
    __syncthreads();
#pragma unroll
    for (int i = 0; i < 2; ++i) {
        const bf16* As = reinterpret_cast<const bf16*>(dsm + i * PJ_STAGE);
        mma_w64(acc, As, As + PJ_AB / 2, wm, wn);
    }
    __syncthreads();
    ep_bf16<1>(acc, dsm, C, HN, nt * 128, mt * 128, tid, wm, wn);
}

// AV: 64-row tiles paired (t64, 31-t64) -> 256 uniform blocks, BK=64.
__global__ __launch_bounds__(128) void k_av64(const bf16* __restrict__ sim,
                                              const bf16* __restrict__ V,
                                              const float* __restrict__ x,
                                              float* __restrict__ out) {
    int vt = blockIdx.x, pair = blockIdx.y, b = blockIdx.z;
    extern __shared__ char dsm[];
    uint32_t sb = smem_u32(dsm);
    int tid = threadIdx.x, wid = tid >> 5;
    int wm = wid & 1, wn = wid >> 1;     // warp tile 32x64 over 64x128 output

    const bf16* Vb = V + (size_t)b * N_ * HDV + vt * 128;
    int tiles2[2] = {31 - pair, pair};   // heavy tile first

#pragma unroll
    for (int t = 0; t < 2; ++t) {
        int t64 = tiles2[t];
        const bf16* Arow = sim + ((size_t)(b * N_ + t64 * 64)) * HN;
        const int nkh = t64 + 1;         // K=64 chunks per head (causal bound)
        const int nk  = nkh * H_;        // >= 8

        FragC acc[2][4];
#pragma unroll
        for (int i = 0; i < 2; ++i)
#pragma unroll
            for (int j = 0; j < 4; ++j) wmma::fill_fragment(acc[i][j], 0.0f);

#pragma unroll
        for (int s = 0; s < 2; ++s) {
            int h = s / nkh, kc = s - h * nkh;
            ld_A64 (sb + s * AV_STAGE, Arow + h * N_ + kc * 64, HN, tid);
            ld_Brow(sb + s * AV_STAGE + AV_A_BYTES,
                    Vb + (size_t)(kc * 64) * HDV + h * DV_, HDV, tid);
            cp_commit();
        }
        for (int i = 0; i < nk; ++i) {
            cp_wait1();
            __syncthreads();
            int ci = i + 2;
            if (ci < nk) {
                int h = ci / nkh, kc = ci - h * nkh;
                uint32_t st = sb + (uint32_t)(ci % 3) * AV_STAGE;
                ld_A64 (st, Arow + h * N_ + kc * 64, HN, tid);
                ld_Brow(st + AV_A_BYTES, Vb + (size_t)(kc * 64) * HDV + h * DV_, HDV, tid);
            }
            cp_commit();
            const bf16* As = reinterpret_cast<const bf16*>(dsm + (i % 3) * AV_STAGE);
            mma_av(acc, As, As + AV_A_BYTES / 2, wm, wn);
        }
        cp_wait0();
        __syncthreads();

        // epilogue: stage 64x136 fp32, residual add, float4 stores
        float* stg = reinterpret_cast<float*>(dsm);
#pragma unroll
        for (int i = 0; i < 2; ++i)
#pragma unroll
            for (int j = 0; j < 4; ++j)
                wmma::store_matrix_sync(stg + (wm * 32 + i * 16) * EP_STRIDE + wn * 64 + j * 16,
                                        acc[i][j], EP_STRIDE, wmma::mem_row_major);
        __syncthreads();
        size_t rowbase = (size_t)(b * N_ + t64 * 64);
#pragma unroll
        for (int it = 0; it < 16; ++it) {
            int idx = it * 128 + tid;
            int r = idx >> 5, cv = idx & 31;
            size_t o = (rowbase + r) * (size_t)DV_ + vt * 128 + cv * 4;
            float4 xv = *reinterpret_cast<const float4*>(x + o);
            const float* p = stg + r * EP_STRIDE + cv * 4;
            float4 ov = make_float4(xv.x + p[0], xv.y + p[1], xv.z + p[2], xv.w + p[3]);
            *reinterpret_cast<float4*>(out + o) = ov;
        }
        __syncthreads();
    }
}

// ---------------- host launcher ---------------------------------------------------
static void conv_launch(const float* src, bf16* dst, int n) {
    int n4 = n / 4;
    int nthread = (n4 + 1) / 2;
    f2bf_kernel<<<(nthread + 255) / 256, 256>>>(
        reinterpret_cast<const float4*>(src),
        reinterpret_cast<__nv_bfloat162*>(dst), n4);
}

extern "C" void kernel_launch(void* const* d_in, const int* in_sizes, int n_in,
                              void* d_out, int out_size) {
    (void)in_sizes; (void)n_in; (void)out_size;
    const float* x  = (const float*)d_in[0];
    const float* Wq = (const float*)d_in[1];
    const float* Wk = (const float*)d_in[2];
    const float* Wv = (const float*)d_in[3];

    bf16 *xb, *wqb, *wkb, *wvb, *Q, *K, *V, *sim;
    cudaGetSymbolAddress((void**)&xb,  g_xb);
    cudaGetSymbolAddress((void**)&wqb, g_wqb);
    cudaGetSymbolAddress((void**)&wkb, g_wkb);
    cudaGetSymbolAddress((void**)&wvb, g_wvb);
    cudaGetSymbolAddress((void**)&Q,   g_Q);
    cudaGetSymbolAddress((void**)&K,   g_K);
    cudaGetSymbolAddress((void**)&V,   g_V);
    cudaGetSymbolAddress((void**)&sim, g_sim);

    cudaFuncSetAttribute(k_proj,   cudaFuncAttributeMaxDynamicSharedMemorySize, PJ_DSMEM);
    cudaFuncSetAttribute(k_scores, cudaFuncAttributeMaxDynamicSharedMemorySize, SC_DSMEM);
    cudaFuncSetAttribute(k_av64,   cudaFuncAttributeMaxDynamicSharedMemorySize, AV_DSMEM);

    conv_launch(x,  xb,  B_ * N_ * D_);
    conv_launch(Wq, wqb, H_ * DK_ * D_);
    conv_launch(Wk, wkb, H_ * DK_ * D_);
    conv_launch(Wv, wvb, H_ * DV_ * D_);

    // Q = x Wq^T, K = x Wk^T, V = x Wv^T
    k_proj<<<dim3(HDK / 128, (B_ * N_) / 128), 128, PJ_DSMEM>>>(xb, wqb, Q, HDK);
    k_proj<<<dim3(HDK / 128, (B_ * N_) / 128), 128, PJ_DSMEM>>>(xb, wkb, K, HDK);
    k_proj<<<dim3(HDV / 128, (B_ * N_) / 128), 128, PJ_DSMEM>>>(xb, wvb, V, HDV);

    // sim = causal relu(Q K^T)/N  (lower-triangle tiles only)
    k_scores<<<dim3(16, 16, 16), 128, SC_DSMEM>>>(Q, K, sim);

    // out = x + sim V  (256 uniform paired blocks, all co-resident)
    k_av64<<<dim3(8, 16, 2), 128, AV_DSMEM>>>(sim, V, x, (float*)d_out);
}

// round 9
// speedup vs baseline: 1.0304x; 1.0304x over previous
#include <cuda_runtime.h>
#include <cuda_bf16.h>
#include <mma.h>
#include <cstdint>

using namespace nvcuda;
using bf16 = __nv_bfloat16;

// ---------------- problem dims --------------------------------------------------
constexpr int B_  = 2;
constexpr int N_  = 2048;
constexpr int D_  = 1024;
constexpr int H_  = 8;
constexpr int DK_ = 128;
constexpr int DV_ = 1024;
constexpr int HDK = H_ * DK_;    // 1024
constexpr int HDV = H_ * DV_;    // 8192
constexpr int HN  = H_ * N_;     // 16384

// ---------------- tiling / smem config -------------------------------------------
constexpr int A_STRIDE = 40;              // K-major stage row stride (elems), BK=32
constexpr int B_ROW_STRIDE = 136;         // row-major B stage row stride (elems)
constexpr int EP_STRIDE = 136;            // fp32 epilogue stage stride

// NT kernels (128x128, BK=32): A 128x40 + B 128x40 per stage
constexpr int STAGE_BYTES = 20480;
constexpr int DSMEM = 4 * STAGE_BYTES;    // 81920 (>= 128x136 fp32 epilogue stage)

// AV (64x128, BK=32): A 64x40 (5120B) + B 32x136 (8704B)
constexpr int AV_A_BYTES = 64 * A_STRIDE * 2;                   // 5120
constexpr int AV_STAGE   = AV_A_BYTES + 32 * B_ROW_STRIDE * 2;  // 13824
constexpr int AV_DSMEM   = 4 * AV_STAGE;                        // 55296 (>= 64x136 fp32)

// ---------------- scratch (__device__ globals) ----------------------------------
__device__ bf16 g_xb [(size_t)B_ * N_ * D_];
__device__ bf16 g_wqb[(size_t)H_ * DK_ * D_];
__device__ bf16 g_wkb[(size_t)H_ * DK_ * D_];
__device__ bf16 g_wvb[(size_t)H_ * DV_ * D_];
__device__ bf16 g_Q  [(size_t)B_ * N_ * HDK];
__device__ bf16 g_K  [(size_t)B_ * N_ * HDK];
__device__ bf16 g_V  [(size_t)B_ * N_ * HDV];
__device__ bf16 g_sim[(size_t)B_ * N_ * HN];   // lower-triangle tiles only

// ---------------- fragment types -------------------------------------------------
using FragA  = wmma::fragment<wmma::matrix_a, 16, 16, 16, bf16, wmma::row_major>;
using FragBc = wmma::fragment<wmma::matrix_b, 16, 16, 16, bf16, wmma::col_major>;
using FragBr = wmma::fragment<wmma::matrix_b, 16, 16, 16, bf16, wmma::row_major>;
using FragC  = wmma::fragment<wmma::accumulator, 16, 16, 16, float>;

// ---------------- cp.async helpers -----------------------------------------------
__device__ __forceinline__ uint32_t smem_u32(const void* p) {
    uint32_t a;
    asm("{ .reg .u64 t; cvta.to.shared.u64 t, %1; cvt.u32.u64 %0, t; }"
        : "=r"(a) : "l"(p));
    return a;
}
__device__ __forceinline__ void cp16(uint32_t dst, const void* src) {
    asm volatile("cp.async.cg.shared.global [%0], [%1], 16;"
                 :: "r"(dst), "l"(__cvta_generic_to_global(src)));
}
__device__ __forceinline__ void cp_commit() {
    asm volatile("cp.async.commit_group;" ::: "memory");
}
__device__ __forceinline__ void cp_wait2() {
    asm volatile("cp.async.wait_group 2;" ::: "memory");
}

// 128 rows x 32 cols K-major (row stride 40 elems), 128 threads, 4 cp16 each
__device__ __forceinline__ void ld_A(uint32_t sdst, const bf16* g, int ld, int tid) {
#pragma unroll
    for (int i = 0; i < 4; ++i) {
        int u = tid + i * 128;
        int r = u >> 2, c = (u & 3) * 8;
        cp16(sdst + (uint32_t)(r * (A_STRIDE * 2) + c * 2), g + (size_t)r * ld + c);
    }
}
// 64 rows x 32 cols K-major (row stride 40 elems), 128 threads, 2 cp16 each
__device__ __forceinline__ void ld_A64(uint32_t sdst, const bf16* g, int ld, int tid) {
#pragma unroll
    for (int i = 0; i < 2; ++i) {
        int u = tid + i * 128;
        int r = u >> 2, c = (u & 3) * 8;
        cp16(sdst + (uint32_t)(r * (A_STRIDE * 2) + c * 2), g + (size_t)r * ld + c);
    }
}
// 32 rows(k) x 128 cols(n) row-major (row stride 136 elems), 128 threads
__device__ __forceinline__ void ld_Brow(uint32_t sdst, const bf16* g, int ld, int tid) {
#pragma unroll
    for (int i = 0; i < 4; ++i) {
        int u = tid + i * 128;
        int r = u >> 4, c = (u & 15) * 8;
        cp16(sdst + (uint32_t)(r * (B_ROW_STRIDE * 2) + c * 2), g + (size_t)r * ld + c);
    }
}

// ---------------- MMA micro-steps --------------------------------------------------
// warp tile 64x64, NT (B col-major view, stride 40)
__device__ __forceinline__ void mma_w64(FragC acc[4][4], const bf16* As, const bf16* Bs,
                                        int wm, int wn) {
#pragma unroll
    for (int ks = 0; ks < 32; ks += 16) {
        FragA a[4];
#pragma unroll
        for (int i = 0; i < 4; ++i)
            wmma::load_matrix_sync(a[i], As + (wm * 64 + i * 16) * A_STRIDE + ks, A_STRIDE);
#pragma unroll
        for (int j = 0; j < 4; ++j) {
            FragBc b;
            wmma::load_matrix_sync(b, Bs + (wn * 64 + j * 16) * A_STRIDE + ks, A_STRIDE);
#pragma unroll
            for (int i = 0; i < 4; ++i)
                wmma::mma_sync(acc[i][j], a[i], b, acc[i][j]);
        }
    }
}
// warp tile 32x64, B row-major (stride 136) — AV
__device__ __forceinline__ void mma_av(FragC acc[2][4], const bf16* As, const bf16* Bs,
                                       int wm, int wn) {
#pragma unroll
    for (int ks = 0; ks < 32; ks += 16) {
        FragA a[2];
        wmma::load_matrix_sync(a[0], As + (wm * 32) * A_STRIDE + ks,      A_STRIDE);
        wmma::load_matrix_sync(a[1], As + (wm * 32 + 16) * A_STRIDE + ks, A_STRIDE);
#pragma unroll
        for (int j = 0; j < 4; ++j) {
            FragBr b;
            wmma::load_matrix_sync(b, Bs + ks * B_ROW_STRIDE + wn * 64 + j * 16, B_ROW_STRIDE);
            wmma::mma_sync(acc[0][j], a[0], b, acc[0][j]);
            wmma::mma_sync(acc[1][j], a[1], b, acc[1][j]);
        }
    }
}

// ---------------- pipelined NT mainloop (128x128, 128 threads) ---------------------
__device__ __forceinline__ void loop_nt(FragC acc[4][4], char* dsm,
                                        const bf16* A, int lda,
                                        const bf16* Bp, int ldb,
                                        int nk, int tid, int wm, int wn) {
    uint32_t sb = smem_u32(dsm);
#pragma unroll
    for (int s = 0; s < 3; ++s) {
        if (s < nk) {
            ld_A(sb + s * STAGE_BYTES,         A  + s * 32, lda, tid);
            ld_A(sb + s * STAGE_BYTES + 10240, Bp + s * 32, ldb, tid);
        }
        cp_commit();
    }
    for (int i = 0; i < nk; ++i) {
        cp_wait2();
        __syncthreads();
        int ci = i + 3;
        if (ci < nk) {
            uint32_t st = sb + (uint32_t)(ci & 3) * STAGE_BYTES;
            ld_A(st,         A  + ci * 32, lda, tid);
            ld_A(st + 10240, Bp + ci * 32, ldb, tid);
        }
        cp_commit();
        const bf16* As = reinterpret_cast<const bf16*>(dsm + (i & 3) * STAGE_BYTES);
        mma_w64(acc, As, As + 10240 / 2, wm, wn);
    }
    __syncthreads();
}

// ---------------- epilogues (128 threads) ------------------------------------------
__device__ __forceinline__ void stage_acc16(FragC acc[4][4], float* stg, int wm, int wn) {
#pragma unroll
    for (int i = 0; i < 4; ++i)
#pragma unroll
        for (int j = 0; j < 4; ++j)
            wmma::store_matrix_sync(stg + (wm * 64 + i * 16) * EP_STRIDE + wn * 64 + j * 16,
                                    acc[i][j], EP_STRIDE, wmma::mem_row_major);
}

// MODE 0: plain bf16. MODE 1: causal relu/N bf16.
template <int MODE>
__device__ __forceinline__ void ep_bf16(FragC acc[4][4], char* dsm, bf16* C, int ldc,
                                        int q0, int m0, int tid, int wm, int wn) {
    float* stg = reinterpret_cast<float*>(dsm);
    stage_acc16(acc, stg, wm, wn);
    __syncthreads();
    const float inv_n = 1.0f / (float)N_;
#pragma unroll
    for (int it = 0; it < 16; ++it) {
        int idx = it * 128 + tid;
        int r = idx >> 4, cv = idx & 15;
        const float* p = stg + r * EP_STRIDE + cv * 8;
        union { bf16 v[8]; uint4 u4; } pk;
#pragma unroll
        for (int e = 0; e < 8; ++e) {
            float v = p[e];
            if (MODE == 1) {
                int gm = m0 + cv * 8 + e;
                v = (gm <= q0 + r) ? fmaxf(v, 0.0f) * inv_n : 0.0f;
            }
            pk.v[e] = __float2bfloat16(v);
        }
        *reinterpret_cast<uint4*>(C + (size_t)r * ldc + cv * 8) = pk.u4;
    }
    __syncthreads();
}

// ---------------- kernels ---------------------------------------------------------
// merged fp32->bf16 conversion of all four tensors (prefix-range partition)
__global__ void conv_all_kernel(const float4* __restrict__ sx,
                                const float4* __restrict__ sq,
                                const float4* __restrict__ sk,
                                const float4* __restrict__ sv,
                                __nv_bfloat162* __restrict__ dx,
                                __nv_bfloat162* __restrict__ dq,
                                __nv_bfloat162* __restrict__ dk,
                                __nv_bfloat162* __restrict__ dv) {
    constexpr int N_X = (B_ * N_ * D_) / 4;          // 1048576
    constexpr int N_Q = (H_ * DK_ * D_) / 4;         // 262144
    constexpr int N_V = (H_ * DV_ * D_) / 4;         // 2097152
    constexpr int T1 = N_X, T2 = T1 + N_Q, T3 = T2 + N_Q, T4 = T3 + N_V;

    int i = blockIdx.x * blockDim.x + threadIdx.x;
    if (i >= T4) return;
    const float4* src; __nv_bfloat162* dst; int j;
    if (i < T1)      { src = sx; dst = dx; j = i; }
    else if (i < T2) { src = sq; dst = dq; j = i - T1; }
    else if (i < T3) { src = sk; dst = dk; j = i - T2; }
    else             { src = sv; dst = dv; j = i - T3; }
    float4 v = src[j];
    dst[2 * j]     = __floats2bfloat162_rn(v.x, v.y);
    dst[2 * j + 1] = __floats2bfloat162_rn(v.z, v.w);
}

// merged Q/K/V projection: bx in [0,8)->Q, [8,16)->K, [16,80)->V
__global__ __launch_bounds__(128) void k_qkv(const bf16* __restrict__ xb,
                                             const bf16* __restrict__ wq,
                                             const bf16* __restrict__ wk,
                                             const bf16* __restrict__ wv,
                                             bf16* __restrict__ Q,
                                             bf16* __restrict__ K,
                                             bf16* __restrict__ V) {
    extern __shared__ char dsm[];
    int tid = threadIdx.x, wid = tid >> 5;
    int wm = wid & 1, wn = wid >> 1;

    int bx = blockIdx.x;
    const bf16* W; bf16* C0; int ldc; int xt;
    if (bx < 8)       { W = wq; C0 = Q; ldc = HDK; xt = bx; }
    else if (bx < 16) { W = wk; C0 = K; ldc = HDK; xt = bx - 8; }
    else              { W = wv; C0 = V; ldc = HDV; xt = bx - 16; }

    const bf16* A  = xb + (size_t)blockIdx.y * 128 * D_;
    const bf16* Bp = W  + (size_t)xt * 128 * D_;
    bf16* C = C0 + (size_t)(blockIdx.y * 128) * ldc + xt * 128;

    FragC acc[4][4];
#pragma unroll
    for (int i = 0; i < 4; ++i)
#pragma unroll
        for (int j = 0; j < 4; ++j) wmma::fill_fragment(acc[i][j], 0.0f);

    loop_nt(acc, dsm, A, D_, Bp, D_, D_ / 32, tid, wm, wn);
    ep_bf16<0>(acc, dsm, C, ldc, 0, 0, tid, wm, wn);
}

__global__ __launch_bounds__(128) void k_scores(const bf16* __restrict__ Q,
                                                const bf16* __restrict__ Kx,
                                                bf16* __restrict__ sim) {
    int mt = blockIdx.x, nt = blockIdx.y;
    if (mt > nt) return;                       // upper tiles never read by AV
    int b = blockIdx.z >> 3, h = blockIdx.z & 7;
    extern __shared__ char dsm[];
    int tid = threadIdx.x, wid = tid >> 5;
    int wm = wid & 1, wn = wid >> 1;

    const bf16* A  = Q  + ((size_t)(b * N_ + nt * 128)) * HDK + h * DK_;
    const bf16* Bp = Kx + ((size_t)(b * N_ + mt * 128)) * HDK + h * DK_;
    bf16* C = sim + ((size_t)(b * N_ + nt * 128)) * HN + (size_t)h * N_ + mt * 128;

    FragC acc[4][4];
#pragma unroll
    for (int i = 0; i < 4; ++i)
#pragma unroll
        for (int j = 0; j < 4; ++j) wmma::fill_fragment(acc[i][j], 0.0f);

    loop_nt(acc, dsm, A, HDK, Bp, HDK, DK_ / 32, tid, wm, wn);
    ep_bf16<1>(acc, dsm, C, HN, nt * 128, mt * 128, tid, wm, wn);
}

// AV: 64-row tiles paired (t64, 31-t64) -> 256 uniform blocks of 33 units each,
// all co-resident (>=2 CTAs/SM, 2 warps/SMSP, zero tail).
__global__ __launch_bounds__(128) void k_av64(const bf16* __restrict__ sim,
                                              const bf16* __restrict__ V,
                                              const float* __restrict__ x,
                                              float* __restrict__ out) {
    int vt = blockIdx.x, pair = blockIdx.y, b = blockIdx.z;
    extern __shared__ char dsm[];
    uint32_t sb = smem_u32(dsm);
    int tid = threadIdx.x, wid = tid >> 5;
    int wm = wid & 1, wn = wid >> 1;     // warp tile 32x64 over 64x128 output

    const bf16* Vb = V + (size_t)b * N_ * HDV + vt * 128;
    int tiles2[2] = {31 - pair, pair};   // heavy tile first

#pragma unroll
    for (int t = 0; t < 2; ++t) {
        int t64 = tiles2[t];
        const bf16* Arow = sim + ((size_t)(b * N_ + t64 * 64)) * HN;
        const int nkh = (t64 + 1) * 2;   // K=32 chunks per head (causal bound)
        const int nk  = nkh * H_;        // >= 16

        FragC acc[2][4];
#pragma unroll
        for (int i = 0; i < 2; ++i)
#pragma unroll
            for (int j = 0; j < 4; ++j) wmma::fill_fragment(acc[i][j], 0.0f);

#pragma unroll
        for (int s = 0; s < 3; ++s) {
            int h = s / nkh, kc = s - h * nkh;
            ld_A64 (sb + s * AV_STAGE, Arow + h * N_ + kc * 32, HN, tid);
            ld_Brow(sb + s * AV_STAGE + AV_A_BYTES,
                    Vb + (size_t)(kc * 32) * HDV + h * DV_, HDV, tid);
            cp_commit();
        }
        for (int i = 0; i < nk; ++i) {
            cp_wait2();
            __syncthreads();
            int ci = i + 3;
            if (ci < nk) {
                int h = ci / nkh, kc = ci - h * nkh;
                uint32_t st = sb + (uint32_t)(ci & 3) * AV_STAGE;
                ld_A64 (st, Arow + h * N_ + kc * 32, HN, tid);
                ld_Brow(st + AV_A_BYTES, Vb + (size_t)(kc * 32) * HDV + h * DV_, HDV, tid);
            }
            cp_commit();
            const bf16* As = reinterpret_cast<const bf16*>(dsm + (i & 3) * AV_STAGE);
            mma_av(acc, As, As + AV_A_BYTES / 2, wm, wn);
        }
        __syncthreads();

        // epilogue: stage 64x136 fp32, residual add, float4 stores
        float* stg = reinterpret_cast<float*>(dsm);
#pragma unroll
        for (int i = 0; i < 2; ++i)
#pragma unroll
            for (int j = 0; j < 4; ++j)
                wmma::store_matrix_sync(stg + (wm * 32 + i * 16) * EP_STRIDE + wn * 64 + j * 16,
                                        acc[i][j], EP_STRIDE, wmma::mem_row_major);
        __syncthreads();
        size_t rowbase = (size_t)(b * N_ + t64 * 64);
#pragma unroll
        for (int it = 0; it < 16; ++it) {
            int idx = it * 128 + tid;
            int r = idx >> 5, cv = idx & 31;
            size_t o = (rowbase + r) * (size_t)DV_ + vt * 128 + cv * 4;
            float4 xv = *reinterpret_cast<const float4*>(x + o);
            const float* p = stg + r * EP_STRIDE + cv * 4;
            float4 ov = make_float4(xv.x + p[0], xv.y + p[1], xv.z + p[2], xv.w + p[3]);
            *reinterpret_cast<float4*>(out + o) = ov;
        }
        __syncthreads();
    }
}

// ---------------- host launcher ---------------------------------------------------
extern "C" void kernel_launch(void* const* d_in, const int* in_sizes, int n_in,
                              void* d_out, int out_size) {
    (void)in_sizes; (void)n_in; (void)out_size;
    const float* x  = (const float*)d_in[0];
    const float* Wq = (const float*)d_in[1];
    const float* Wk = (const float*)d_in[2];
    const float* Wv = (const float*)d_in[3];

    bf16 *xb, *wqb, *wkb, *wvb, *Q, *K, *V, *sim;
    cudaGetSymbolAddress((void**)&xb,  g_xb);
    cudaGetSymbolAddress((void**)&wqb, g_wqb);
    cudaGetSymbolAddress((void**)&wkb, g_wkb);
    cudaGetSymbolAddress((void**)&wvb, g_wvb);
    cudaGetSymbolAddress((void**)&Q,   g_Q);
    cudaGetSymbolAddress((void**)&K,   g_K);
    cudaGetSymbolAddress((void**)&V,   g_V);
    cudaGetSymbolAddress((void**)&sim, g_sim);

    cudaFuncSetAttribute(k_qkv,    cudaFuncAttributeMaxDynamicSharedMemorySize, DSMEM);
    cudaFuncSetAttribute(k_scores, cudaFuncAttributeMaxDynamicSharedMemorySize, DSMEM);
    cudaFuncSetAttribute(k_av64,   cudaFuncAttributeMaxDynamicSharedMemorySize, AV_DSMEM);

    // one conversion launch for x, Wq, Wk, Wv
    constexpr int TOT4 = (B_ * N_ * D_ + 2 * H_ * DK_ * D_ + H_ * DV_ * D_) / 4;
    conv_all_kernel<<<(TOT4 + 255) / 256, 256>>>(
        reinterpret_cast<const float4*>(x),
        reinterpret_cast<const float4*>(Wq),
        reinterpret_cast<const float4*>(Wk),
        reinterpret_cast<const float4*>(Wv),
        reinterpret_cast<__nv_bfloat162*>(xb),
        reinterpret_cast<__nv_bfloat162*>(wqb),
        reinterpret_cast<__nv_bfloat162*>(wkb),
        reinterpret_cast<__nv_bfloat162*>(wvb));

    // one merged projection launch: Q, K, V  (2560 blocks)
    k_qkv<<<dim3(80, (B_ * N_) / 128), 128, DSMEM>>>(xb, wqb, wkb, wvb, Q, K, V);

    // sim = causal relu(Q K^T)/N  (lower-triangle tiles only)
    k_scores<<<dim3(16, 16, 16), 128, DSMEM>>>(Q, K, sim);

    // out = x + sim V  (256 uniform paired blocks, all co-resident)
    k_av64<<<dim3(8, 16, 2), 128, AV_DSMEM>>>(sim, V, x, (float*)d_out);
}